// round 4
// baseline (speedup 1.0000x reference)
#include <cuda_runtime.h>
#include <cfloat>

// PoolingLayer: out[p, f] = max_k features[neighbor_indices[p, k], f]
// N=100000, NP=50000, K=32, F=128
// Inputs (metadata order): points (N,3) f32 [unused], features (N,128) f32,
//                          neighbor_indices (NP,32) int32 (JAX downcasts int64
//                          to int32 without x64 mode). Output (NP,128) f32.

#define NPTS  100000
#define NP_OUT 50000
#define KNBR 32
#define FDIM 128          // 128 floats = 32 float4 per row

__device__ __forceinline__ float4 fmax4(float4 a, float4 b) {
    a.x = fmaxf(a.x, b.x);
    a.y = fmaxf(a.y, b.y);
    a.z = fmaxf(a.z, b.z);
    a.w = fmaxf(a.w, b.w);
    return a;
}

__global__ __launch_bounds__(256)
void pool_max_kernel(const float4* __restrict__ feats,   // (N, 32) float4
                     const int* __restrict__ nbr,        // (NP, 32) int32
                     float4* __restrict__ out)            // (NP, 32) float4
{
    const int gtid = blockIdx.x * blockDim.x + threadIdx.x;
    const int warp = gtid >> 5;          // one warp per output point
    const int lane = gtid & 31;          // one float4 column per lane
    if (warp >= NP_OUT) return;

    // Coalesced load of this output point's 32 neighbor indices (one per lane).
    int my_idx = nbr[(size_t)warp * KNBR + lane];
    // Safety clamp: no-op on valid data, prevents illegal access on bad data.
    my_idx = min(max(my_idx, 0), NPTS - 1);

    const float4 NEG = make_float4(-FLT_MAX, -FLT_MAX, -FLT_MAX, -FLT_MAX);
    float4 acc0 = NEG, acc1 = NEG, acc2 = NEG, acc3 = NEG;

    // 32 neighbors, 4 independent accumulator chains for MLP/ILP.
    #pragma unroll
    for (int k = 0; k < KNBR; k += 4) {
        const int i0 = __shfl_sync(0xffffffffu, my_idx, k + 0);
        const int i1 = __shfl_sync(0xffffffffu, my_idx, k + 1);
        const int i2 = __shfl_sync(0xffffffffu, my_idx, k + 2);
        const int i3 = __shfl_sync(0xffffffffu, my_idx, k + 3);
        float4 v0 = feats[(size_t)i0 * (FDIM / 4) + lane];
        float4 v1 = feats[(size_t)i1 * (FDIM / 4) + lane];
        float4 v2 = feats[(size_t)i2 * (FDIM / 4) + lane];
        float4 v3 = feats[(size_t)i3 * (FDIM / 4) + lane];
        acc0 = fmax4(acc0, v0);
        acc1 = fmax4(acc1, v1);
        acc2 = fmax4(acc2, v2);
        acc3 = fmax4(acc3, v3);
    }

    acc0 = fmax4(acc0, acc1);
    acc2 = fmax4(acc2, acc3);
    acc0 = fmax4(acc0, acc2);

    out[(size_t)warp * (FDIM / 4) + lane] = acc0;
}

extern "C" void kernel_launch(void* const* d_in, const int* in_sizes, int n_in,
                              void* d_out, int out_size) {
    // d_in[0] = points (unused), d_in[1] = features, d_in[2] = neighbor_indices
    const float4* feats = (const float4*)d_in[1];
    const int* nbr = (const int*)d_in[2];
    float4* out = (float4*)d_out;

    const int total_threads = NP_OUT * 32;      // one warp per output point
    const int block = 256;
    const int grid = (total_threads + block - 1) / block;
    pool_max_kernel<<<grid, block>>>(feats, nbr, out);
}